// round 3
// baseline (speedup 1.0000x reference)
#include <cuda_runtime.h>
#include <math.h>

// Problem constants
#define BSZ   2048
#define TT    96
#define DIN   64
#define HH    256
#define KSEG  20

// ---------------- device scratch ----------------
__device__ float g_hb0[BSZ * 512];   // ping-pong h buffers: [b][0:256]=h0, [256:512]=h1
__device__ float g_hb1[BSZ * 512];
__device__ float g_c0[BSZ * HH];
__device__ float g_c1[BSZ * HH];
__device__ float g_W0[1024 * 320];   // gate-interleaved rows: n' = 4h+g
__device__ float g_W1[1024 * 512];
__device__ float g_b0[1024];
__device__ float g_b1[1024];
__device__ float g_Wp[21 * 512];     // permuted projection weights for hcat layout
__device__ float g_pb[21];

// ---------------- init ----------------
__global__ void zero_state(float* out) {
    int i = blockIdx.x * blockDim.x + threadIdx.x;
    if (i < BSZ * 512) { g_hb0[i] = 0.f; g_hb1[i] = 0.f; }
    if (i < BSZ * HH)  { g_c0[i] = 0.f;  g_c1[i] = 0.f; }
    if (i == 0) out[0] = 0.f;
}

__global__ void build_weights(
    const float* __restrict__ Wih0, const float* __restrict__ Whh0,
    const float* __restrict__ Wih1, const float* __restrict__ Whh1,
    const float* __restrict__ bih0, const float* __restrict__ bhh0,
    const float* __restrict__ bih1, const float* __restrict__ bhh1,
    const float* __restrict__ Wpb,  const float* __restrict__ bpb,
    const float* __restrict__ Wpg,  const float* __restrict__ bpg)
{
    int i = blockIdx.x * blockDim.x + threadIdx.x;
    if (i < 1024 * 320) {
        int np = i / 320, k = i % 320;
        int n = (np & 3) * 256 + (np >> 2);               // gate-interleave
        g_W0[i] = (k < 64) ? Wih0[n * 64 + k] : Whh0[n * 256 + (k - 64)];
    }
    if (i < 1024 * 512) {
        int np = i / 512, k = i % 512;
        int n = (np & 3) * 256 + (np >> 2);
        g_W1[i] = (k < 256) ? Wih1[n * 256 + k] : Whh1[n * 256 + (k - 256)];
    }
    if (i < 21 * 512) {
        int m = i / 512, k = i % 512;
        int src = 2 * (k & 255) + (k >> 8);               // hp[2j+l] = hcat[j+256l]
        g_Wp[i] = (m == 0) ? Wpb[src] : Wpg[(m - 1) * 512 + src];
    }
    if (i < 1024) {
        int n = (i & 3) * 256 + (i >> 2);
        g_b0[i] = bih0[n] + bhh0[n];
        g_b1[i] = bih1[n] + bhh1[n];
    }
    if (i < 21) g_pb[i] = (i == 0) ? bpb[0] : bpg[i - 1];
}

// ---------------- fused GEMM + LSTM cell ----------------
// MODE 0: z = [x_t | h0_prev] @ W0'^T + b0 ; cell -> h0_new, c0   (K=320)
// MODE 1: z = [h0_new | h1_prev] @ W1'^T + b1 ; cell -> h1_new, c1 (K=512)
#define BK 16

__device__ __forceinline__ void tile_mma(
    const float (*as)[132], const float (*bs)[132],
    float acc[8][8], int tx, int ty)
{
#pragma unroll
    for (int k = 0; k < BK; k++) {
        float4 a0 = *(const float4*)&as[k][ty * 8];
        float4 a1 = *(const float4*)&as[k][ty * 8 + 4];
        float4 b0 = *(const float4*)&bs[k][tx * 8];
        float4 b1 = *(const float4*)&bs[k][tx * 8 + 4];
        float ra[8] = {a0.x, a0.y, a0.z, a0.w, a1.x, a1.y, a1.z, a1.w};
        float rb[8] = {b0.x, b0.y, b0.z, b0.w, b1.x, b1.y, b1.z, b1.w};
#pragma unroll
        for (int r = 0; r < 8; r++)
#pragma unroll
            for (int c = 0; c < 8; c++) acc[r][c] += ra[r] * rb[c];
    }
}

__device__ __forceinline__ float fsig(float x)  { return 1.f / (1.f + __expf(-x)); }
__device__ __forceinline__ float ftanh(float x) { return 2.f / (1.f + __expf(-2.f * x)) - 1.f; }

template <int MODE>
__global__ __launch_bounds__(256, 2)
void gemm_step(const float* __restrict__ xt, int rd)
{
    constexpr int K = (MODE == 0) ? 320 : 512;
    const float* __restrict__ W    = (MODE == 0) ? g_W0 : g_W1;
    const float* __restrict__ bias = (MODE == 0) ? g_b0 : g_b1;
    const float* hA = rd ? g_hb1 : g_hb0;   // previous step state
    float*       hB = rd ? g_hb0 : g_hb1;   // this step state
    float*     cbuf = (MODE == 0) ? g_c0 : g_c1;

    __shared__ __align__(16) float As[2][BK][132];
    __shared__ __align__(16) float Bs[2][BK][132];

    const int tid  = threadIdx.x;
    const int row0 = blockIdx.y * 128;
    const int col0 = blockIdx.x * 128;

    const int a_m = tid & 127;
    const int a_k = (tid >> 7) * 8;
    const int tx = tid & 15;
    const int ty = tid >> 4;

    const float* xrow  = xt + (size_t)(row0 + a_m) * (TT * DIN);
    const float* harow = hA + (size_t)(row0 + a_m) * 512;
    const float* hbrow = hB + (size_t)(row0 + a_m) * 512;
    const float* wrow  = W  + (size_t)(col0 + a_m) * K + a_k;

    float acc[8][8];
#pragma unroll
    for (int r = 0; r < 8; r++)
#pragma unroll
        for (int c = 0; c < 8; c++) acc[r][c] = 0.f;

    // ---- prologue: tile k0 = 0 ----
    {
        const float* pA = (MODE == 0) ? (xrow + a_k) : (hbrow + a_k);
        float4 a0v = *(const float4*)pA;
        float4 a1v = *(const float4*)(pA + 4);
        float4 b0v = *(const float4*)wrow;
        float4 b1v = *(const float4*)(wrow + 4);
        As[0][a_k + 0][a_m] = a0v.x; As[0][a_k + 1][a_m] = a0v.y;
        As[0][a_k + 2][a_m] = a0v.z; As[0][a_k + 3][a_m] = a0v.w;
        As[0][a_k + 4][a_m] = a1v.x; As[0][a_k + 5][a_m] = a1v.y;
        As[0][a_k + 6][a_m] = a1v.z; As[0][a_k + 7][a_m] = a1v.w;
        Bs[0][a_k + 0][a_m] = b0v.x; Bs[0][a_k + 1][a_m] = b0v.y;
        Bs[0][a_k + 2][a_m] = b0v.z; Bs[0][a_k + 3][a_m] = b0v.w;
        Bs[0][a_k + 4][a_m] = b1v.x; Bs[0][a_k + 5][a_m] = b1v.y;
        Bs[0][a_k + 6][a_m] = b1v.z; Bs[0][a_k + 7][a_m] = b1v.w;
    }
    __syncthreads();

    int buf = 0;
#pragma unroll 1
    for (int k0 = BK; k0 < K; k0 += BK) {
        // prefetch next tile into registers
        const float* pA;
        if (MODE == 0) pA = (k0 < 64)  ? (xrow + k0 + a_k) : (harow + (k0 - 64) + a_k);
        else           pA = (k0 < 256) ? (hbrow + k0 + a_k) : (harow + k0 + a_k);
        float4 na0 = *(const float4*)pA;
        float4 na1 = *(const float4*)(pA + 4);
        float4 nb0 = *(const float4*)(wrow + k0);
        float4 nb1 = *(const float4*)(wrow + k0 + 4);

        tile_mma(As[buf], Bs[buf], acc, tx, ty);

        int nb = buf ^ 1;
        As[nb][a_k + 0][a_m] = na0.x; As[nb][a_k + 1][a_m] = na0.y;
        As[nb][a_k + 2][a_m] = na0.z; As[nb][a_k + 3][a_m] = na0.w;
        As[nb][a_k + 4][a_m] = na1.x; As[nb][a_k + 5][a_m] = na1.y;
        As[nb][a_k + 6][a_m] = na1.z; As[nb][a_k + 7][a_m] = na1.w;
        Bs[nb][a_k + 0][a_m] = nb0.x; Bs[nb][a_k + 1][a_m] = nb0.y;
        Bs[nb][a_k + 2][a_m] = nb0.z; Bs[nb][a_k + 3][a_m] = nb0.w;
        Bs[nb][a_k + 4][a_m] = nb1.x; Bs[nb][a_k + 5][a_m] = nb1.y;
        Bs[nb][a_k + 6][a_m] = nb1.z; Bs[nb][a_k + 7][a_m] = nb1.w;
        __syncthreads();
        buf = nb;
    }
    tile_mma(As[buf], Bs[buf], acc, tx, ty);

    // ---- fused epilogue: bias + LSTM cell ----
    float4 bi0 = *(const float4*)&bias[col0 + tx * 8];
    float4 bi1 = *(const float4*)&bias[col0 + tx * 8 + 4];
    float bre[8] = {bi0.x, bi0.y, bi0.z, bi0.w, bi1.x, bi1.y, bi1.z, bi1.w};
    const int hbase = (col0 + tx * 8) >> 2;      // first of 2 h-units (even)
    float* hout = hB + (MODE == 0 ? 0 : 256);

#pragma unroll
    for (int r = 0; r < 8; r++) {
        int m = row0 + ty * 8 + r;
        float2 cold = *(const float2*)(cbuf + (size_t)m * HH + hbase);
        float hv[2], cv[2];
#pragma unroll
        for (int p = 0; p < 2; p++) {
            float zi = acc[r][p * 4 + 0] + bre[p * 4 + 0];
            float zf = acc[r][p * 4 + 1] + bre[p * 4 + 1];
            float zg = acc[r][p * 4 + 2] + bre[p * 4 + 2];
            float zo = acc[r][p * 4 + 3] + bre[p * 4 + 3];
            float co = p ? cold.y : cold.x;
            float c2 = fsig(zf) * co + fsig(zi) * ftanh(zg);
            cv[p] = c2;
            hv[p] = fsig(zo) * ftanh(c2);
        }
        *(float2*)(cbuf + (size_t)m * HH + hbase) = make_float2(cv[0], cv[1]);
        *(float2*)(hout + (size_t)m * 512 + hbase) = make_float2(hv[0], hv[1]);
    }
}

// ---------------- projection + softplus + CRPS ----------------
__device__ __forceinline__ float softplusf(float x) {
    return fmaxf(x, 0.f) + log1pf(expf(-fabsf(x)));
}

__global__ void proj_crps(const float* __restrict__ labels, int t, int rd,
                          float* __restrict__ out)
{
    int b = blockIdx.x;
    int lane = threadIdx.x;
    const float* hrow = (rd ? g_hb0 : g_hb1) + (size_t)b * 512;

    float hreg[16];
#pragma unroll
    for (int j = 0; j < 16; j++) hreg[j] = hrow[lane + 32 * j];

    __shared__ float sp[21];
    for (int m = 0; m < 21; m++) {
        const float* w = g_Wp + m * 512;
        float a = 0.f;
#pragma unroll
        for (int j = 0; j < 16; j++) a += hreg[j] * w[lane + 32 * j];
#pragma unroll
        for (int o = 16; o; o >>= 1) a += __shfl_xor_sync(0xFFFFFFFFu, a, o);
        if (lane == 0) sp[m] = softplusf(a + g_pb[m]);
    }
    __syncwarp();

    if (lane == 0) {
        const float invk = 1.0f / (float)KSEG;
        float beta0 = sp[0];
        float g[KSEG];
#pragma unroll
        for (int j = 0; j < KSEG; j++) g[j] = sp[1 + j];

        float braw[KSEG];
        braw[0] = (g[0] - beta0) * (0.5f * KSEG);
#pragma unroll
        for (int i = 1; i < KSEG; i++) braw[i] = (g[i] - g[i - 1]) * (0.5f * KSEG);
        float bb[KSEG];
        bb[0] = braw[0];
#pragma unroll
        for (int i = 1; i < KSEG; i++) bb[i] = braw[i] - braw[i - 1];
        float ssum = 0.f;
#pragma unroll
        for (int i = 0; i < KSEG - 1; i++) ssum += bb[i];
        bb[KSEG - 1] = g[KSEG - 1] - ssum;

        float F[KSEG];
        for (int i = 0; i < KSEG; i++) {
            float acc = (float)(i + 1) * invk * beta0;
            for (int j = 0; j <= i; j++) {
                float d = (float)(i + 1 - j) * invk;
                acc += d * d * bb[j];
            }
            F[i] = acc;
        }

        float y = labels[b * TT + t];
        float A = 0.f, Bc = beta0, C = -y;
        float mind = 1e30f; int amin = 0;
        unsigned almask = 0;
        for (int i = 0; i < KSEG; i++) {
            float knot = (i == 0) ? 0.f : F[i - 1];
            float diff = y - knot;
            float ad = fabsf(diff);
            if (ad < mind) { mind = ad; amin = i; }
            if (diff > 0.f) {
                almask |= (1u << i);
                float ksi = (float)i * invk;
                A += bb[i];
                Bc -= 2.f * bb[i] * ksi;
                C += bb[i] * ksi * ksi;
            }
        }
        float disc = Bc * Bc - 4.f * A * C;
        float alpha;
        if (A != 0.f && disc >= 0.f)       alpha = (-Bc + sqrtf(disc)) / (2.f * A);
        else if (A == 0.f)                 alpha = -C / ((Bc == 0.f) ? 1.f : Bc);
        else                               alpha = (float)amin * invk;

        float crps = -y * (1.f - 2.f * alpha) + beta0 * (1.f / 3.f - alpha * alpha);
        for (int i = 0; i < KSEG; i++) {
            float ksi = (float)i * invk;
            float om = 1.f - ksi;
            crps += bb[i] * (1.f / 6.f) * om * om * om * om;
            if ((almask >> i) & 1u) {
                float d = alpha - ksi;
                crps -= (2.f / 3.f) * bb[i] * d * d * d;
            }
        }
        atomicAdd(out, crps * (1.0f / (float)BSZ));
    }
}

// ---------------- host launch ----------------
extern "C" void kernel_launch(void* const* d_in, const int* in_sizes, int n_in,
                              void* d_out, int out_size)
{
    const float* train  = (const float*)d_in[0];
    const float* labels = (const float*)d_in[1];
    const float* Wih0 = (const float*)d_in[2];
    const float* Whh0 = (const float*)d_in[3];
    const float* Wih1 = (const float*)d_in[4];
    const float* Whh1 = (const float*)d_in[5];
    const float* bih0 = (const float*)d_in[6];
    const float* bhh0 = (const float*)d_in[7];
    const float* bih1 = (const float*)d_in[8];
    const float* bhh1 = (const float*)d_in[9];
    const float* Wpb  = (const float*)d_in[10];
    const float* bpb  = (const float*)d_in[11];
    const float* Wpg  = (const float*)d_in[12];
    const float* bpg  = (const float*)d_in[13];
    float* out = (float*)d_out;

    zero_state<<<(BSZ * 512 + 255) / 256, 256>>>(out);
    build_weights<<<(1024 * 512 + 255) / 256, 256>>>(
        Wih0, Whh0, Wih1, Whh1, bih0, bhh0, bih1, bhh1, Wpb, bpb, Wpg, bpg);

    dim3 grid(1024 / 128, 2048 / 128);   // (8, 16)
    for (int t = 0; t < TT; t++) {
        int rd = t & 1;
        gemm_step<0><<<grid, 256>>>(train + (size_t)t * DIN, rd);
        gemm_step<1><<<grid, 256>>>(train, rd);
        proj_crps<<<BSZ, 32>>>(labels, t, rd, out);
    }
}

// round 4
// speedup vs baseline: 1.1061x; 1.1061x over previous
#include <cuda_runtime.h>
#include <math.h>
#include <stdint.h>

// Problem constants
#define BSZ   2048
#define TT    96
#define DIN   64
#define HH    256
#define KSEG  20

// GEMM tiling
#define BM 128
#define BN 128
#define BK 16
#define NTHREADS 256          // 8 warps, 2(M) x 4(N), warp tile 64x32

// smem layout (floats): A: 2 buf x 2 half x (16*136); B: 2 buf x 2 half x (128*20)
#define ASTR 136
#define BSTR 20
#define A_HALF (BK * ASTR)            // 2176
#define B_HALF (BN * BSTR)            // 2560
#define B_BASE (4 * A_HALF)           // 8704
#define SMEM_FLOATS (B_BASE + 4 * B_HALF)   // 18944
#define SMEM_BYTES (SMEM_FLOATS * 4)        // 75776

// ---------------- device scratch ----------------
__device__ float g_hb0[BSZ * 512];   // ping-pong h: [b][0:256]=h0, [256:512]=h1
__device__ float g_hb1[BSZ * 512];
__device__ float g_c0[BSZ * HH];
__device__ float g_c1[BSZ * HH];
__device__ float g_W0h[1024 * 320];  // gate-interleaved (n'=4h+g), tf32 hi/lo split
__device__ float g_W0l[1024 * 320];
__device__ float g_W1h[1024 * 512];
__device__ float g_W1l[1024 * 512];
__device__ float g_b0[1024];
__device__ float g_b1[1024];
__device__ float g_Wp[21 * 512];
__device__ float g_pb[21];

// ---------------- tf32 helpers ----------------
__device__ __forceinline__ uint32_t f2tf32(float x) {
    uint32_t r;
    asm("cvt.rna.tf32.f32 %0, %1;" : "=r"(r) : "f"(x));
    return r;
}
__device__ __forceinline__ void split_tf32(float x, float& hi, float& lo) {
    uint32_t h = f2tf32(x);
    hi = __uint_as_float(h);
    lo = __uint_as_float(f2tf32(x - hi));
}
__device__ __forceinline__ void mma_tf32(float* d, const uint32_t* a, const uint32_t* b) {
    asm volatile(
        "mma.sync.aligned.m16n8k8.row.col.f32.tf32.tf32.f32 "
        "{%0,%1,%2,%3}, {%4,%5,%6,%7}, {%8,%9}, {%0,%1,%2,%3};\n"
        : "+f"(d[0]), "+f"(d[1]), "+f"(d[2]), "+f"(d[3])
        : "r"(a[0]), "r"(a[1]), "r"(a[2]), "r"(a[3]), "r"(b[0]), "r"(b[1]));
}
__device__ __forceinline__ int mperm(int m) {   // pair rows g and g+8 within 16-blocks
    return (m & ~15) | ((m & 7) << 1) | ((m >> 3) & 1);
}
__device__ __forceinline__ int kperm(int k) {   // pair k=t and k=t+4 within 8-blocks
    return (k & 8) | ((k & 3) << 1) | ((k >> 2) & 1);
}

// ---------------- init ----------------
__global__ void zero_state(float* out) {
    int i = blockIdx.x * blockDim.x + threadIdx.x;
    if (i < BSZ * 512) { g_hb0[i] = 0.f; g_hb1[i] = 0.f; }
    if (i < BSZ * HH)  { g_c0[i] = 0.f;  g_c1[i] = 0.f; }
    if (i == 0) out[0] = 0.f;
}

__global__ void build_weights(
    const float* __restrict__ Wih0, const float* __restrict__ Whh0,
    const float* __restrict__ Wih1, const float* __restrict__ Whh1,
    const float* __restrict__ bih0, const float* __restrict__ bhh0,
    const float* __restrict__ bih1, const float* __restrict__ bhh1,
    const float* __restrict__ Wpb,  const float* __restrict__ bpb,
    const float* __restrict__ Wpg,  const float* __restrict__ bpg)
{
    int i = blockIdx.x * blockDim.x + threadIdx.x;
    if (i < 1024 * 320) {
        int np = i / 320, k = i % 320;
        int n = (np & 3) * 256 + (np >> 2);               // gate-interleave
        float v = (k < 64) ? Wih0[n * 64 + k] : Whh0[n * 256 + (k - 64)];
        float h, l; split_tf32(v, h, l);
        g_W0h[i] = h; g_W0l[i] = l;
    }
    if (i < 1024 * 512) {
        int np = i / 512, k = i % 512;
        int n = (np & 3) * 256 + (np >> 2);
        float v = (k < 256) ? Wih1[n * 256 + k] : Whh1[n * 256 + (k - 256)];
        float h, l; split_tf32(v, h, l);
        g_W1h[i] = h; g_W1l[i] = l;
    }
    if (i < 21 * 512) {
        int m = i / 512, k = i % 512;
        int src = 2 * (k & 255) + (k >> 8);
        g_Wp[i] = (m == 0) ? Wpb[src] : Wpg[(m - 1) * 512 + src];
    }
    if (i < 1024) {
        int n = (i & 3) * 256 + (i >> 2);
        g_b0[i] = bih0[n] + bhh0[n];
        g_b1[i] = bih1[n] + bhh1[n];
    }
    if (i < 21) g_pb[i] = (i == 0) ? bpb[0] : bpg[i - 1];
}

__device__ __forceinline__ float fsig(float x)  { return 1.f / (1.f + __expf(-x)); }
__device__ __forceinline__ float ftanh(float x) { return 2.f / (1.f + __expf(-2.f * x)) - 1.f; }

// ---------------- fused tensor-core GEMM + LSTM cell ----------------
// MODE 0: z = [x_t | h0_prev] @ W0'^T + b0  -> h0_new, c0   (K=320)
// MODE 1: z = [h0_new | h1_prev] @ W1'^T + b1 -> h1_new, c1 (K=512)
template <int MODE>
__global__ void __launch_bounds__(NTHREADS)
gemm_step(const float* __restrict__ xt, int rd)
{
    constexpr int K = (MODE == 0) ? 320 : 512;
    const float* __restrict__ Wh   = (MODE == 0) ? g_W0h : g_W1h;
    const float* __restrict__ Wl   = (MODE == 0) ? g_W0l : g_W1l;
    const float* __restrict__ bias = (MODE == 0) ? g_b0 : g_b1;
    const float* hA = rd ? g_hb1 : g_hb0;
    float*       hB = rd ? g_hb0 : g_hb1;
    float*     cbuf = (MODE == 0) ? g_c0 : g_c1;

    extern __shared__ float sm[];

    const int tid  = threadIdx.x;
    const int row0 = blockIdx.y * BM;
    const int col0 = blockIdx.x * BN;

    // cooperative-load ids
    const int am   = tid & 127;
    const int aks  = (tid >> 7) * 8;      // k 0..7 or 8..15
    const int ampi = mperm(am);
    const int bn   = tid >> 1;            // 0..127
    const int bks  = (tid & 1) * 8;

    const float* xrow  = xt + (size_t)(row0 + am) * (TT * DIN);
    const float* harow = hA + (size_t)(row0 + am) * 512;
    const float* hbrow = hB + (size_t)(row0 + am) * 512;
    const float* wrh   = Wh + (size_t)(col0 + bn) * K + bks;
    const float* wrl   = Wl + (size_t)(col0 + bn) * K + bks;

    // fragment ids
    const int lane = tid & 31, warp = tid >> 5;
    const int g = lane >> 2, t = lane & 3;
    const int wm = warp >> 2;             // 0..1 (M)
    const int wn = warp & 3;              // 0..3 (N)

    float acc[4][4][4];
#pragma unroll
    for (int i = 0; i < 4; i++)
#pragma unroll
        for (int j = 0; j < 4; j++)
#pragma unroll
            for (int r = 0; r < 4; r++) acc[i][j][r] = 0.f;

    float4 va0, va1, vbh0, vbh1, vbl0, vbl1;

    // ---- A/B gmem tile fetch into registers ----
    auto fetch = [&](int k0) {
        const float* pA;
        if (MODE == 0) pA = (k0 < 64)  ? (xrow + k0) : (harow + (k0 - 64));
        else           pA = (k0 < 256) ? (hbrow + k0) : (harow + k0);
        va0 = *(const float4*)(pA + aks);
        va1 = *(const float4*)(pA + aks + 4);
        vbh0 = *(const float4*)(wrh + k0);
        vbh1 = *(const float4*)(wrh + k0 + 4);
        vbl0 = *(const float4*)(wrl + k0);
        vbl1 = *(const float4*)(wrl + k0 + 4);
    };
    // ---- store registers -> smem tile (with tf32 split of A) ----
    auto stage = [&](int buf) {
        float* Ah = sm + (buf * 2) * A_HALF;
        float* Al = Ah + A_HALF;
        float* Bh = sm + B_BASE + (buf * 2) * B_HALF;
        float* Bl = Bh + B_HALF;
        float av[8] = {va0.x, va0.y, va0.z, va0.w, va1.x, va1.y, va1.z, va1.w};
#pragma unroll
        for (int c = 0; c < 8; c++) {
            float h, l; split_tf32(av[c], h, l);
            Ah[(aks + c) * ASTR + ampi] = h;
            Al[(aks + c) * ASTR + ampi] = l;
        }
        float bvh[8] = {vbh0.x, vbh0.y, vbh0.z, vbh0.w, vbh1.x, vbh1.y, vbh1.z, vbh1.w};
        float bvl[8] = {vbl0.x, vbl0.y, vbl0.z, vbl0.w, vbl1.x, vbl1.y, vbl1.z, vbl1.w};
#pragma unroll
        for (int c = 0; c < 8; c++) {
            int kp = kperm(bks + c);
            Bh[bn * BSTR + kp] = bvh[c];
            Bl[bn * BSTR + kp] = bvl[c];
        }
    };
    // ---- compute one k-tile from smem ----
    auto compute = [&](int buf) {
        const float* Ah = sm + (buf * 2) * A_HALF;
        const float* Al = Ah + A_HALF;
        const float* Bh = sm + B_BASE + (buf * 2) * B_HALF;
        const float* Bl = Bh + B_HALF;
#pragma unroll
        for (int s = 0; s < 2; s++) {
            const int kb = s * 8;
            uint32_t af[4][4];
#pragma unroll
            for (int i = 0; i < 4; i++) {
                int mi = wm * 64 + i * 16 + 2 * g;
                float2 p0 = *(const float2*)&Ah[(kb + t) * ASTR + mi];
                float2 p1 = *(const float2*)&Ah[(kb + t + 4) * ASTR + mi];
                af[i][0] = __float_as_uint(p0.x); af[i][1] = __float_as_uint(p0.y);
                af[i][2] = __float_as_uint(p1.x); af[i][3] = __float_as_uint(p1.y);
            }
            uint32_t bh[4][2], bl[4][2];
#pragma unroll
            for (int j = 0; j < 4; j++) {
                int nb = (wn * 32 + j * 8 + g) * BSTR + kb + 2 * t;
                float2 q = *(const float2*)&Bh[nb];
                float2 r = *(const float2*)&Bl[nb];
                bh[j][0] = __float_as_uint(q.x); bh[j][1] = __float_as_uint(q.y);
                bl[j][0] = __float_as_uint(r.x); bl[j][1] = __float_as_uint(r.y);
            }
#pragma unroll
            for (int i = 0; i < 4; i++)
#pragma unroll
                for (int j = 0; j < 4; j++) {
                    mma_tf32(acc[i][j], af[i], bh[j]);
                    mma_tf32(acc[i][j], af[i], bl[j]);
                }
            // reload A-lo frags (reuse registers)
#pragma unroll
            for (int i = 0; i < 4; i++) {
                int mi = wm * 64 + i * 16 + 2 * g;
                float2 p0 = *(const float2*)&Al[(kb + t) * ASTR + mi];
                float2 p1 = *(const float2*)&Al[(kb + t + 4) * ASTR + mi];
                af[i][0] = __float_as_uint(p0.x); af[i][1] = __float_as_uint(p0.y);
                af[i][2] = __float_as_uint(p1.x); af[i][3] = __float_as_uint(p1.y);
            }
#pragma unroll
            for (int i = 0; i < 4; i++)
#pragma unroll
                for (int j = 0; j < 4; j++)
                    mma_tf32(acc[i][j], af[i], bh[j]);
        }
    };

    // ---- pipelined main loop ----
    fetch(0);
    stage(0);
    __syncthreads();
    int buf = 0;
#pragma unroll 1
    for (int k0 = BK; k0 < K; k0 += BK) {
        fetch(k0);
        compute(buf);
        stage(buf ^ 1);
        __syncthreads();
        buf ^= 1;
    }
    compute(buf);

    // ---- fused LSTM epilogue ----
    // acc[i][j]: c0=(g,2t) c1=(g,2t+1) c2=(g+8,2t) c3=(g+8,2t+1) within
    // (m = wm*64+i*16, n = wn*32+j*8). Lane^1 shuffle reassembles gate quads.
    const bool ev = (lane & 1) == 0;
    int ncol[2], hidx[2];
    float4 bs4[2];
#pragma unroll
    for (int jj = 0; jj < 2; jj++) {
        ncol[jj] = ev ? (wn * 32 + jj * 8 + 2 * t)
                      : (wn * 32 + (jj + 2) * 8 + 2 * (t - 1));
        bs4[jj] = *(const float4*)&bias[col0 + ncol[jj]];
        hidx[jj] = (col0 + ncol[jj]) >> 2;
    }
    float* hout = hB + (MODE == 0 ? 0 : 256);

#pragma unroll
    for (int i = 0; i < 4; i++) {
#pragma unroll
        for (int rh = 0; rh < 2; rh++) {
            int m = row0 + wm * 64 + i * 16 + g + rh * 8;
#pragma unroll
            for (int jj = 0; jj < 2; jj++) {
                float s0 = ev ? acc[i][jj + 2][rh * 2]     : acc[i][jj][rh * 2];
                float s1 = ev ? acc[i][jj + 2][rh * 2 + 1] : acc[i][jj][rh * 2 + 1];
                float r0 = __shfl_xor_sync(0xFFFFFFFFu, s0, 1);
                float r1 = __shfl_xor_sync(0xFFFFFFFFu, s1, 1);
                float zi, zf, zg, zo;
                if (ev) { zi = acc[i][jj][rh * 2]; zf = acc[i][jj][rh * 2 + 1]; zg = r0; zo = r1; }
                else    { zi = r0; zf = r1; zg = acc[i][jj + 2][rh * 2]; zo = acc[i][jj + 2][rh * 2 + 1]; }
                zi += bs4[jj].x; zf += bs4[jj].y; zg += bs4[jj].z; zo += bs4[jj].w;
                float cold = cbuf[(size_t)m * HH + hidx[jj]];
                float c2 = fsig(zf) * cold + fsig(zi) * ftanh(zg);
                cbuf[(size_t)m * HH + hidx[jj]] = c2;
                hout[(size_t)m * 512 + hidx[jj]] = fsig(zo) * ftanh(c2);
            }
        }
    }
}

// ---------------- projection + softplus + CRPS ----------------
__device__ __forceinline__ float softplusf(float x) {
    return fmaxf(x, 0.f) + log1pf(expf(-fabsf(x)));
}

__global__ void proj_crps(const float* __restrict__ labels, int t, int rd,
                          float* __restrict__ out)
{
    int b = blockIdx.x;
    int lane = threadIdx.x;
    const float* hrow = (rd ? g_hb0 : g_hb1) + (size_t)b * 512;

    float hreg[16];
#pragma unroll
    for (int j = 0; j < 16; j++) hreg[j] = hrow[lane + 32 * j];

    __shared__ float sp[21];
    for (int m = 0; m < 21; m++) {
        const float* w = g_Wp + m * 512;
        float a = 0.f;
#pragma unroll
        for (int j = 0; j < 16; j++) a += hreg[j] * w[lane + 32 * j];
#pragma unroll
        for (int o = 16; o; o >>= 1) a += __shfl_xor_sync(0xFFFFFFFFu, a, o);
        if (lane == 0) sp[m] = softplusf(a + g_pb[m]);
    }
    __syncwarp();

    if (lane == 0) {
        const float invk = 1.0f / (float)KSEG;
        float beta0 = sp[0];
        float g[KSEG];
#pragma unroll
        for (int j = 0; j < KSEG; j++) g[j] = sp[1 + j];

        float braw[KSEG];
        braw[0] = (g[0] - beta0) * (0.5f * KSEG);
#pragma unroll
        for (int i = 1; i < KSEG; i++) braw[i] = (g[i] - g[i - 1]) * (0.5f * KSEG);
        float bb[KSEG];
        bb[0] = braw[0];
#pragma unroll
        for (int i = 1; i < KSEG; i++) bb[i] = braw[i] - braw[i - 1];
        float ssum = 0.f;
#pragma unroll
        for (int i = 0; i < KSEG - 1; i++) ssum += bb[i];
        bb[KSEG - 1] = g[KSEG - 1] - ssum;

        float F[KSEG];
        for (int i = 0; i < KSEG; i++) {
            float acc = (float)(i + 1) * invk * beta0;
            for (int j = 0; j <= i; j++) {
                float d = (float)(i + 1 - j) * invk;
                acc += d * d * bb[j];
            }
            F[i] = acc;
        }

        float y = labels[b * TT + t];
        float A = 0.f, Bc = beta0, C = -y;
        float mind = 1e30f; int amin = 0;
        unsigned almask = 0;
        for (int i = 0; i < KSEG; i++) {
            float knot = (i == 0) ? 0.f : F[i - 1];
            float diff = y - knot;
            float ad = fabsf(diff);
            if (ad < mind) { mind = ad; amin = i; }
            if (diff > 0.f) {
                almask |= (1u << i);
                float ksi = (float)i * invk;
                A += bb[i];
                Bc -= 2.f * bb[i] * ksi;
                C += bb[i] * ksi * ksi;
            }
        }
        float disc = Bc * Bc - 4.f * A * C;
        float alpha;
        if (A != 0.f && disc >= 0.f)       alpha = (-Bc + sqrtf(disc)) / (2.f * A);
        else if (A == 0.f)                 alpha = -C / ((Bc == 0.f) ? 1.f : Bc);
        else                               alpha = (float)amin * invk;

        float crps = -y * (1.f - 2.f * alpha) + beta0 * (1.f / 3.f - alpha * alpha);
        for (int i = 0; i < KSEG; i++) {
            float ksi = (float)i * invk;
            float om = 1.f - ksi;
            crps += bb[i] * (1.f / 6.f) * om * om * om * om;
            if ((almask >> i) & 1u) {
                float d = alpha - ksi;
                crps -= (2.f / 3.f) * bb[i] * d * d * d;
            }
        }
        atomicAdd(out, crps * (1.0f / (float)BSZ));
    }
}

// ---------------- host launch ----------------
extern "C" void kernel_launch(void* const* d_in, const int* in_sizes, int n_in,
                              void* d_out, int out_size)
{
    const float* train  = (const float*)d_in[0];
    const float* labels = (const float*)d_in[1];
    const float* Wih0 = (const float*)d_in[2];
    const float* Whh0 = (const float*)d_in[3];
    const float* Wih1 = (const float*)d_in[4];
    const float* Whh1 = (const float*)d_in[5];
    const float* bih0 = (const float*)d_in[6];
    const float* bhh0 = (const float*)d_in[7];
    const float* bih1 = (const float*)d_in[8];
    const float* bhh1 = (const float*)d_in[9];
    const float* Wpb  = (const float*)d_in[10];
    const float* bpb  = (const float*)d_in[11];
    const float* Wpg  = (const float*)d_in[12];
    const float* bpg  = (const float*)d_in[13];
    float* out = (float*)d_out;

    cudaFuncSetAttribute(gemm_step<0>, cudaFuncAttributeMaxDynamicSharedMemorySize, SMEM_BYTES);
    cudaFuncSetAttribute(gemm_step<1>, cudaFuncAttributeMaxDynamicSharedMemorySize, SMEM_BYTES);

    zero_state<<<(BSZ * 512 + 255) / 256, 256>>>(out);
    build_weights<<<(1024 * 512 + 255) / 256, 256>>>(
        Wih0, Whh0, Wih1, Whh1, bih0, bhh0, bih1, bhh1, Wpb, bpb, Wpg, bpg);

    dim3 grid(BN == 128 ? 8 : 16, 2048 / BM);   // (8, 16) = 128 CTAs
    for (int t = 0; t < TT; t++) {
        int rd = t & 1;
        gemm_step<0><<<grid, NTHREADS, SMEM_BYTES>>>(train + (size_t)t * DIN, rd);
        gemm_step<1><<<grid, NTHREADS, SMEM_BYTES>>>(train, rd);
        proj_crps<<<BSZ, 32>>>(labels, t, rd, out);
    }
}

// round 7
// speedup vs baseline: 1.3081x; 1.1826x over previous
#include <cuda_runtime.h>
#include <cuda_bf16.h>
#include <math.h>
#include <stdint.h>

// Problem constants
#define BSZ   2048
#define TT    96
#define DIN   64
#define HH    256
#define KSEG  20

// GEMM tile: 64(M) x 128(N), BK=32, 2-stage cp.async pipeline
#define NTHREADS 256
// smem stage layout (bytes): Ahi[64x40bf16], Alo, Bhi[128x40bf16], Blo
#define OFF_AHI 0
#define OFF_ALO 5120
#define OFF_BHI 10240
#define OFF_BLO 20480
#define STAGE_B 30720
#define SMEM_REQ (2 * STAGE_B + 64)

// ---------------- device scratch ----------------
__device__ __nv_bfloat16 g_xh[BSZ * TT * DIN];
__device__ __nv_bfloat16 g_xl[BSZ * TT * DIN];
__device__ __nv_bfloat16 g_W0h[1024 * 320];   // gate-interleaved n'=4h+g, K-major
__device__ __nv_bfloat16 g_W0l[1024 * 320];
__device__ __nv_bfloat16 g_W1h[1024 * 512];
__device__ __nv_bfloat16 g_W1l[1024 * 512];
__device__ float g_b0[1024];
__device__ float g_b1[1024];
__device__ float g_Wp[21 * 512];
__device__ float g_pb[21];
__device__ float g_c0[BSZ * HH];
__device__ float g_c1[BSZ * HH];
// ping-pong h state, bf16 hi/lo: [b][0:256]=h0, [256:512]=h1
__device__ __nv_bfloat16 g_hhi0[BSZ * 512];
__device__ __nv_bfloat16 g_hlo0[BSZ * 512];
__device__ __nv_bfloat16 g_hhi1[BSZ * 512];
__device__ __nv_bfloat16 g_hlo1[BSZ * 512];

// ---------------- helpers ----------------
__device__ __forceinline__ uint32_t smem_u32(const void* p) {
    uint32_t a;
    asm("{ .reg .u64 t; cvta.to.shared.u64 t, %1; cvt.u32.u64 %0, t; }" : "=r"(a) : "l"(p));
    return a;
}
__device__ __forceinline__ void cp16(uint32_t dst, const void* src) {
    asm volatile("cp.async.cg.shared.global [%0], [%1], 16;" :: "r"(dst), "l"(src));
}
__device__ __forceinline__ void ldm_x4(uint32_t* r, uint32_t addr) {
    asm volatile("ldmatrix.sync.aligned.m8n8.x4.shared.b16 {%0,%1,%2,%3}, [%4];"
        : "=r"(r[0]), "=r"(r[1]), "=r"(r[2]), "=r"(r[3]) : "r"(addr));
}
__device__ __forceinline__ void mma_bf16(float* d, const uint32_t* a, const uint32_t* b) {
    asm volatile(
        "mma.sync.aligned.m16n8k16.row.col.f32.bf16.bf16.f32 "
        "{%0,%1,%2,%3}, {%4,%5,%6,%7}, {%8,%9}, {%0,%1,%2,%3};"
        : "+f"(d[0]), "+f"(d[1]), "+f"(d[2]), "+f"(d[3])
        : "r"(a[0]), "r"(a[1]), "r"(a[2]), "r"(a[3]), "r"(b[0]), "r"(b[1]));
}
__device__ __forceinline__ void bf16_split(float v, __nv_bfloat16& hi, __nv_bfloat16& lo) {
    hi = __float2bfloat16(v);
    lo = __float2bfloat16(v - __bfloat162float(hi));
}
__device__ __forceinline__ float fsig(float x)  { return 1.f / (1.f + __expf(-x)); }
__device__ __forceinline__ float ftanh(float x) { return 2.f / (1.f + __expf(-2.f * x)) - 1.f; }

// ---------------- init kernels ----------------
__global__ void zero_state(float* out) {
    int i = blockIdx.x * blockDim.x + threadIdx.x;
    if (i < BSZ * 512) {
        __nv_bfloat16 z = __float2bfloat16(0.f);
        g_hhi0[i] = z; g_hlo0[i] = z; g_hhi1[i] = z; g_hlo1[i] = z;
    }
    if (i < BSZ * HH) { g_c0[i] = 0.f; g_c1[i] = 0.f; }
    if (i == 0) out[0] = 0.f;
}

__global__ void presplit_x(const float* __restrict__ train) {
    int i = blockIdx.x * blockDim.x + threadIdx.x;
    if (i < BSZ * TT * DIN) {
        __nv_bfloat16 h, l;
        bf16_split(train[i], h, l);
        g_xh[i] = h; g_xl[i] = l;
    }
}

__global__ void build_weights(
    const float* __restrict__ Wih0, const float* __restrict__ Whh0,
    const float* __restrict__ Wih1, const float* __restrict__ Whh1,
    const float* __restrict__ bih0, const float* __restrict__ bhh0,
    const float* __restrict__ bih1, const float* __restrict__ bhh1,
    const float* __restrict__ Wpb,  const float* __restrict__ bpb,
    const float* __restrict__ Wpg,  const float* __restrict__ bpg)
{
    int i = blockIdx.x * blockDim.x + threadIdx.x;
    if (i < 1024 * 320) {
        int np = i / 320, k = i % 320;
        int n = (np & 3) * 256 + (np >> 2);
        float v = (k < 64) ? Wih0[n * 64 + k] : Whh0[n * 256 + (k - 64)];
        bf16_split(v, g_W0h[i], g_W0l[i]);
    }
    if (i < 1024 * 512) {
        int np = i / 512, k = i % 512;
        int n = (np & 3) * 256 + (np >> 2);
        float v = (k < 256) ? Wih1[n * 256 + k] : Whh1[n * 256 + (k - 256)];
        bf16_split(v, g_W1h[i], g_W1l[i]);
    }
    if (i < 21 * 512) {
        int m = i / 512, k = i % 512;
        int src = 2 * (k & 255) + (k >> 8);
        g_Wp[i] = (m == 0) ? Wpb[src] : Wpg[(m - 1) * 512 + src];
    }
    if (i < 1024) {
        int n = (i & 3) * 256 + (i >> 2);
        g_b0[i] = bih0[n] + bhh0[n];
        g_b1[i] = bih1[n] + bhh1[n];
    }
    if (i < 21) g_pb[i] = (i == 0) ? bpb[0] : bpg[i - 1];
}

// ---------------- fused bf16x3 mma GEMM + LSTM cell ----------------
// MODE 0: z = [x_t | h0_prev] @ W0'^T + b0 -> h0,c0   (K=320)
// MODE 1: z = [h0_new | h1_prev] @ W1'^T + b1 -> h1,c1 (K=512)
template <int MODE>
__global__ void __launch_bounds__(NTHREADS, 2)
gemm_step(int rd, int t)
{
    constexpr int K = (MODE == 0) ? 320 : 512;
    constexpr int S = K / 32;
    const __nv_bfloat16* __restrict__ Wh = (MODE == 0) ? g_W0h : g_W1h;
    const __nv_bfloat16* __restrict__ Wl = (MODE == 0) ? g_W0l : g_W1l;
    const float* __restrict__ bias = (MODE == 0) ? g_b0 : g_b1;
    const __nv_bfloat16* hAhi = rd ? g_hhi1 : g_hhi0;   // previous-step state
    const __nv_bfloat16* hAlo = rd ? g_hlo1 : g_hlo0;
    __nv_bfloat16* hBhi = rd ? g_hhi0 : g_hhi1;         // this-step state
    __nv_bfloat16* hBlo = rd ? g_hlo0 : g_hlo1;
    float* cbuf = (MODE == 0) ? g_c0 : g_c1;
    const __nv_bfloat16* xh = g_xh + t * 64;
    const __nv_bfloat16* xl = g_xl + t * 64;

    extern __shared__ float smraw[];
    const uint32_t AB = smem_u32(smraw);

    const int tid = threadIdx.x;
    const int lane = tid & 31, warp = tid >> 5;
    const int wm = warp >> 2;             // 0..1 (M)
    const int wn = warp & 3;              // 0..3 (N)
    const int g = lane >> 2, tq = lane & 3;
    const int row0 = blockIdx.y * 64;     // batch rows
    const int col0 = blockIdx.x * 128;    // gate cols (n')

    float acc[2][4][4];
#pragma unroll
    for (int i = 0; i < 2; i++)
#pragma unroll
        for (int j = 0; j < 4; j++)
#pragma unroll
            for (int r = 0; r < 4; r++) acc[i][j][r] = 0.f;

    // ---- stage loader: one BK=32 chunk into buffer (s&1) ----
    auto stage_load = [&](int s) {
        const uint32_t bb = AB + (uint32_t)(s & 1) * STAGE_B;
        const __nv_bfloat16 *ah, *al;
        int lda, koff;
        if (MODE == 0) {
            if (s < 2) { ah = xh; al = xl; lda = TT * DIN; koff = s * 32; }
            else       { ah = hAhi; al = hAlo; lda = 512; koff = (s - 2) * 32; }
        } else {
            if (s < 8) { ah = hBhi; al = hBlo; }
            else       { ah = hAhi; al = hAlo; }
            lda = 512; koff = s * 32;
        }
        {   // A: 64 rows x 4 x 16B
            int row = tid >> 2, c = tid & 3;
            uint32_t d = bb + row * 80 + c * 16;
            size_t so = (size_t)(row0 + row) * lda + koff + c * 8;
            cp16(d + OFF_AHI, ah + so);
            cp16(d + OFF_ALO, al + so);
        }
        // B: 128 rows x 4 x 16B
#pragma unroll
        for (int rr = 0; rr < 2; rr++) {
            int pos = rr * 256 + tid;
            int row = pos >> 2, c = pos & 3;
            uint32_t d = bb + row * 80 + c * 16;
            size_t wo = (size_t)(col0 + row) * K + s * 32 + c * 8;
            cp16(d + OFF_BHI, Wh + wo);
            cp16(d + OFF_BLO, Wl + wo);
        }
        asm volatile("cp.async.commit_group;");
    };

    // ---- compute one staged BK=32 chunk ----
    auto compute = [&](int buf) {
        const uint32_t base = AB + (uint32_t)buf * STAGE_B;
#pragma unroll
        for (int kk = 0; kk < 32; kk += 16) {
            uint32_t ahi[2][4], alo[2][4];
#pragma unroll
            for (int i = 0; i < 2; i++) {
                uint32_t row = wm * 32 + i * 16 + (lane & 15);
                uint32_t cb = (kk + ((lane >> 4) << 3)) * 2;
                ldm_x4(ahi[i], base + OFF_AHI + row * 80 + cb);
                ldm_x4(alo[i], base + OFF_ALO + row * 80 + cb);
            }
            uint32_t bhi[2][4], blo[2][4];
#pragma unroll
            for (int jp = 0; jp < 2; jp++) {
                uint32_t row = wn * 32 + jp * 16 + (lane & 7) + ((lane >> 4) << 3);
                uint32_t cb = (kk + (((lane >> 3) & 1) << 3)) * 2;
                ldm_x4(bhi[jp], base + OFF_BHI + row * 80 + cb);
                ldm_x4(blo[jp], base + OFF_BLO + row * 80 + cb);
            }
#pragma unroll
            for (int i = 0; i < 2; i++)
#pragma unroll
                for (int j = 0; j < 4; j++) {
                    const uint32_t* bh = &bhi[j >> 1][(j & 1) * 2];
                    const uint32_t* bl = &blo[j >> 1][(j & 1) * 2];
                    mma_bf16(acc[i][j], ahi[i], bh);
                    mma_bf16(acc[i][j], ahi[i], bl);
                    mma_bf16(acc[i][j], alo[i], bh);
                }
        }
    };

    // ---- 2-stage pipeline ----
    stage_load(0);
#pragma unroll 1
    for (int s = 0; s < S; s++) {
        if (s + 1 < S) {
            stage_load(s + 1);
            asm volatile("cp.async.wait_group 1;" ::: "memory");
        } else {
            asm volatile("cp.async.wait_group 0;" ::: "memory");
        }
        __syncthreads();
        compute(s & 1);
        __syncthreads();
    }

    // ---- fused LSTM epilogue ----
    // acc[i][j]: c0,c1=(m=g, n=2t,2t+1), c2,c3=(m=g+8, same n) at
    // (m = wm*32+i*16, n' = wn*32+j*8). lane^1 shuffle reassembles gate quads.
    const bool ev = (tq & 1) == 0;
    const int mrow = row0 + wm * 32 + g + (ev ? 0 : 8);
    __nv_bfloat16* hhout = hBhi + (MODE == 0 ? 0 : 256);
    __nv_bfloat16* hlout = hBlo + (MODE == 0 ? 0 : 256);
#pragma unroll
    for (int i = 0; i < 2; i++) {
        const int m = mrow + i * 16;
#pragma unroll
        for (int j = 0; j < 4; j++) {
            float* a = acc[i][j];
            float s0 = ev ? a[2] : a[0];
            float s1 = ev ? a[3] : a[1];
            float r0 = __shfl_xor_sync(0xFFFFFFFFu, s0, 1);
            float r1 = __shfl_xor_sync(0xFFFFFFFFu, s1, 1);
            float zi = ev ? a[0] : r0;
            float zf = ev ? a[1] : r1;
            float zg = ev ? r0 : a[2];
            float zo = ev ? r1 : a[3];
            int ul = wn * 8 + j * 2 + (tq >> 1);
            float4 bz = *(const float4*)(bias + col0 + 4 * ul);
            int ug = (col0 >> 2) + ul;
            zi += bz.x; zf += bz.y; zg += bz.z; zo += bz.w;
            float cold = cbuf[(size_t)m * HH + ug];
            float c2 = fsig(zf) * cold + fsig(zi) * ftanh(zg);
            float hv = fsig(zo) * ftanh(c2);
            cbuf[(size_t)m * HH + ug] = c2;
            __nv_bfloat16 hh, hl;
            bf16_split(hv, hh, hl);
            hhout[(size_t)m * 512 + ug] = hh;
            hlout[(size_t)m * 512 + ug] = hl;
        }
    }
}

// ---------------- projection + softplus + CRPS ----------------
__device__ __forceinline__ float softplusf(float x) {
    return fmaxf(x, 0.f) + log1pf(expf(-fabsf(x)));
}

__global__ void proj_crps(const float* __restrict__ labels, int t, int rd,
                          float* __restrict__ out)
{
    int b = blockIdx.x;
    int lane = threadIdx.x;
    const __nv_bfloat16* hhi = (rd ? g_hhi0 : g_hhi1) + (size_t)b * 512;
    const __nv_bfloat16* hlo = (rd ? g_hlo0 : g_hlo1) + (size_t)b * 512;

    float hreg[16];
#pragma unroll
    for (int j = 0; j < 16; j++)
        hreg[j] = __bfloat162float(hhi[lane + 32 * j]) + __bfloat162float(hlo[lane + 32 * j]);

    __shared__ float sp[21];
    for (int m = 0; m < 21; m++) {
        const float* wv = g_Wp + m * 512;
        float a = 0.f;
#pragma unroll
        for (int j = 0; j < 16; j++) a += hreg[j] * wv[lane + 32 * j];
#pragma unroll
        for (int o = 16; o; o >>= 1) a += __shfl_xor_sync(0xFFFFFFFFu, a, o);
        if (lane == 0) sp[m] = softplusf(a + g_pb[m]);
    }
    __syncwarp();

    if (lane == 0) {
        const float invk = 1.0f / (float)KSEG;
        float beta0 = sp[0];
        float g[KSEG];
#pragma unroll
        for (int j = 0; j < KSEG; j++) g[j] = sp[1 + j];

        float braw[KSEG];
        braw[0] = (g[0] - beta0) * (0.5f * KSEG);
#pragma unroll
        for (int i = 1; i < KSEG; i++) braw[i] = (g[i] - g[i - 1]) * (0.5f * KSEG);
        float bb[KSEG];
        bb[0] = braw[0];
#pragma unroll
        for (int i = 1; i < KSEG; i++) bb[i] = braw[i] - braw[i - 1];
        float ssum = 0.f;
#pragma unroll
        for (int i = 0; i < KSEG - 1; i++) ssum += bb[i];
        bb[KSEG - 1] = g[KSEG - 1] - ssum;

        float F[KSEG];
        for (int i = 0; i < KSEG; i++) {
            float acc = (float)(i + 1) * invk * beta0;
            for (int j = 0; j <= i; j++) {
                float d = (float)(i + 1 - j) * invk;
                acc += d * d * bb[j];
            }
            F[i] = acc;
        }

        float y = labels[b * TT + t];
        float A = 0.f, Bc = beta0, C = -y;
        float mind = 1e30f; int amin = 0;
        unsigned almask = 0;
        for (int i = 0; i < KSEG; i++) {
            float knot = (i == 0) ? 0.f : F[i - 1];
            float diff = y - knot;
            float ad = fabsf(diff);
            if (ad < mind) { mind = ad; amin = i; }
            if (diff > 0.f) {
                almask |= (1u << i);
                float ksi = (float)i * invk;
                A += bb[i];
                Bc -= 2.f * bb[i] * ksi;
                C += bb[i] * ksi * ksi;
            }
        }
        float disc = Bc * Bc - 4.f * A * C;
        float alpha;
        if (A != 0.f && disc >= 0.f)       alpha = (-Bc + sqrtf(disc)) / (2.f * A);
        else if (A == 0.f)                 alpha = -C / ((Bc == 0.f) ? 1.f : Bc);
        else                               alpha = (float)amin * invk;

        float crps = -y * (1.f - 2.f * alpha) + beta0 * (1.f / 3.f - alpha * alpha);
        for (int i = 0; i < KSEG; i++) {
            float ksi = (float)i * invk;
            float om = 1.f - ksi;
            crps += bb[i] * (1.f / 6.f) * om * om * om * om;
            if ((almask >> i) & 1u) {
                float d = alpha - ksi;
                crps -= (2.f / 3.f) * bb[i] * d * d * d;
            }
        }
        atomicAdd(out, crps * (1.0f / (float)BSZ));
    }
}

// ---------------- host launch ----------------
extern "C" void kernel_launch(void* const* d_in, const int* in_sizes, int n_in,
                              void* d_out, int out_size)
{
    const float* train  = (const float*)d_in[0];
    const float* labels = (const float*)d_in[1];
    const float* Wih0 = (const float*)d_in[2];
    const float* Whh0 = (const float*)d_in[3];
    const float* Wih1 = (const float*)d_in[4];
    const float* Whh1 = (const float*)d_in[5];
    const float* bih0 = (const float*)d_in[6];
    const float* bhh0 = (const float*)d_in[7];
    const float* bih1 = (const float*)d_in[8];
    const float* bhh1 = (const float*)d_in[9];
    const float* Wpb  = (const float*)d_in[10];
    const float* bpb  = (const float*)d_in[11];
    const float* Wpg  = (const float*)d_in[12];
    const float* bpg  = (const float*)d_in[13];
    float* out = (float*)d_out;

    cudaFuncSetAttribute(gemm_step<0>, cudaFuncAttributeMaxDynamicSharedMemorySize, SMEM_REQ);
    cudaFuncSetAttribute(gemm_step<1>, cudaFuncAttributeMaxDynamicSharedMemorySize, SMEM_REQ);

    zero_state<<<(BSZ * 512 + 255) / 256, 256>>>(out);
    presplit_x<<<(BSZ * TT * DIN + 255) / 256, 256>>>(train);
    build_weights<<<(1024 * 512 + 255) / 256, 256>>>(
        Wih0, Whh0, Wih1, Whh1, bih0, bhh0, bih1, bhh1, Wpb, bpb, Wpg, bpg);

    dim3 grid(8, 32);   // (N tiles of 128, M tiles of 64) = 256 CTAs
    for (int t = 0; t < TT; t++) {
        int rd = t & 1;
        gemm_step<0><<<grid, NTHREADS, SMEM_REQ>>>(rd, t);
        gemm_step<1><<<grid, NTHREADS, SMEM_REQ>>>(rd, t);
        proj_crps<<<BSZ, 32>>>(labels, t, rd, out);
    }
}

// round 8
// speedup vs baseline: 1.6938x; 1.2948x over previous
#include <cuda_runtime.h>
#include <cuda_fp16.h>
#include <math.h>
#include <stdint.h>

// Problem constants
#define BSZ   2048
#define TT    96
#define DIN   64
#define HH    256
#define KSEG  20

// GEMM tile: 64(M) x 128(N), BK=32, 4-buffer depth-2 cp.async pipeline
#define NTHREADS 256
// smem stage layout (bytes): A[64 rows x 80B], B[128 rows x 80B]
#define OFF_A   0
#define OFF_B   5120
#define STAGE_B 15360
#define NBUF    4
#define SMEM_REQ (NBUF * STAGE_B + 64)

// ---------------- device scratch ----------------
__device__ __half g_x[BSZ * TT * DIN];
__device__ __half g_W0[1024 * 320];   // gate-interleaved n'=4h+g, K-major
__device__ __half g_W1[1024 * 512];
__device__ float g_b0[1024];
__device__ float g_b1[1024];
__device__ float g_Wp[21 * 512];
__device__ float g_pb[21];
__device__ float g_c0[BSZ * HH];
__device__ float g_c1[BSZ * HH];
// ping-pong h state: [b][0:256]=h0, [256:512]=h1
__device__ __half g_h0[BSZ * 512];
__device__ __half g_h1[BSZ * 512];

// ---------------- helpers ----------------
__device__ __forceinline__ uint32_t smem_u32(const void* p) {
    uint32_t a;
    asm("{ .reg .u64 t; cvta.to.shared.u64 t, %1; cvt.u32.u64 %0, t; }" : "=r"(a) : "l"(p));
    return a;
}
__device__ __forceinline__ void cp16(uint32_t dst, const void* src) {
    asm volatile("cp.async.cg.shared.global [%0], [%1], 16;" :: "r"(dst), "l"(src));
}
__device__ __forceinline__ void ldm_x4(uint32_t* r, uint32_t addr) {
    asm volatile("ldmatrix.sync.aligned.m8n8.x4.shared.b16 {%0,%1,%2,%3}, [%4];"
        : "=r"(r[0]), "=r"(r[1]), "=r"(r[2]), "=r"(r[3]) : "r"(addr));
}
__device__ __forceinline__ void mma_fp16(float* d, const uint32_t* a, const uint32_t* b) {
    asm volatile(
        "mma.sync.aligned.m16n8k16.row.col.f32.f16.f16.f32 "
        "{%0,%1,%2,%3}, {%4,%5,%6,%7}, {%8,%9}, {%0,%1,%2,%3};"
        : "+f"(d[0]), "+f"(d[1]), "+f"(d[2]), "+f"(d[3])
        : "r"(a[0]), "r"(a[1]), "r"(a[2]), "r"(a[3]), "r"(b[0]), "r"(b[1]));
}
__device__ __forceinline__ float fsig(float x)  { return 1.f / (1.f + __expf(-x)); }
__device__ __forceinline__ float ftanh(float x) { return 2.f / (1.f + __expf(-2.f * x)) - 1.f; }

// ---------------- init kernels ----------------
__global__ void zero_state(float* out) {
    int i = blockIdx.x * blockDim.x + threadIdx.x;
    if (i < BSZ * 512) {
        __half z = __float2half(0.f);
        g_h0[i] = z; g_h1[i] = z;
    }
    if (i < BSZ * HH) { g_c0[i] = 0.f; g_c1[i] = 0.f; }
    if (i == 0) out[0] = 0.f;
}

__global__ void presplit_x(const float* __restrict__ train) {
    int i = blockIdx.x * blockDim.x + threadIdx.x;
    if (i < BSZ * TT * DIN) g_x[i] = __float2half(train[i]);
}

__global__ void build_weights(
    const float* __restrict__ Wih0, const float* __restrict__ Whh0,
    const float* __restrict__ Wih1, const float* __restrict__ Whh1,
    const float* __restrict__ bih0, const float* __restrict__ bhh0,
    const float* __restrict__ bih1, const float* __restrict__ bhh1,
    const float* __restrict__ Wpb,  const float* __restrict__ bpb,
    const float* __restrict__ Wpg,  const float* __restrict__ bpg)
{
    int i = blockIdx.x * blockDim.x + threadIdx.x;
    if (i < 1024 * 320) {
        int np = i / 320, k = i % 320;
        int n = (np & 3) * 256 + (np >> 2);               // gate-interleave
        float v = (k < 64) ? Wih0[n * 64 + k] : Whh0[n * 256 + (k - 64)];
        g_W0[i] = __float2half(v);
    }
    if (i < 1024 * 512) {
        int np = i / 512, k = i % 512;
        int n = (np & 3) * 256 + (np >> 2);
        float v = (k < 256) ? Wih1[n * 256 + k] : Whh1[n * 256 + (k - 256)];
        g_W1[i] = __float2half(v);
    }
    if (i < 21 * 512) {
        int m = i / 512, k = i % 512;
        int src = 2 * (k & 255) + (k >> 8);               // hp[2j+l] = hcat[j+256l]
        g_Wp[i] = (m == 0) ? Wpb[src] : Wpg[(m - 1) * 512 + src];
    }
    if (i < 1024) {
        int n = (i & 3) * 256 + (i >> 2);
        g_b0[i] = bih0[n] + bhh0[n];
        g_b1[i] = bih1[n] + bhh1[n];
    }
    if (i < 21) g_pb[i] = (i == 0) ? bpb[0] : bpg[i - 1];
}

// ---------------- fused fp16 mma GEMM + LSTM cell ----------------
// MODE 0: z = [x_t | h0_prev] @ W0'^T + b0 -> h0,c0   (K=320)
// MODE 1: z = [h0_new | h1_prev] @ W1'^T + b1 -> h1,c1 (K=512)
template <int MODE>
__global__ void __launch_bounds__(NTHREADS, 3)
gemm_step(int rd, int t)
{
    constexpr int K = (MODE == 0) ? 320 : 512;
    constexpr int S = K / 32;
    const __half* __restrict__ W    = (MODE == 0) ? g_W0 : g_W1;
    const float* __restrict__ bias  = (MODE == 0) ? g_b0 : g_b1;
    const __half* hA = rd ? g_h1 : g_h0;     // previous-step state
    __half*       hB = rd ? g_h0 : g_h1;     // this-step state
    float* cbuf = (MODE == 0) ? g_c0 : g_c1;
    const __half* xp = g_x + t * 64;

    extern __shared__ float smraw[];
    const uint32_t AB = smem_u32(smraw);

    const int tid = threadIdx.x;
    const int lane = tid & 31, warp = tid >> 5;
    const int wm = warp >> 2;             // 0..1 (M)
    const int wn = warp & 3;              // 0..3 (N)
    const int g = lane >> 2, tq = lane & 3;
    const int row0 = blockIdx.y * 64;     // batch rows
    const int col0 = blockIdx.x * 128;    // gate cols (n')

    float acc[2][4][4];
#pragma unroll
    for (int i = 0; i < 2; i++)
#pragma unroll
        for (int j = 0; j < 4; j++)
#pragma unroll
            for (int r = 0; r < 4; r++) acc[i][j][r] = 0.f;

    // ---- stage loader: one BK=32 chunk into buffer (s & 3) ----
    auto stage_load = [&](int s) {
        const uint32_t bb = AB + (uint32_t)(s & 3) * STAGE_B;
        const __half* ah;
        int lda, koff;
        if (MODE == 0) {
            if (s < 2) { ah = xp; lda = TT * DIN; koff = s * 32; }
            else       { ah = hA; lda = 512;      koff = (s - 2) * 32; }
        } else {
            ah = (s < 8) ? hB : hA;   // [h0_new | h1_prev]
            lda = 512; koff = s * 32;
        }
        {   // A: 64 rows x 4 x 16B = 256 chunks, one per thread
            int row = tid >> 2, c = tid & 3;
            cp16(bb + OFF_A + row * 80 + c * 16,
                 ah + (size_t)(row0 + row) * lda + koff + c * 8);
        }
        // B: 128 rows x 4 x 16B = 512 chunks, two per thread
#pragma unroll
        for (int rr = 0; rr < 2; rr++) {
            int pos = rr * 256 + tid;
            int row = pos >> 2, c = pos & 3;
            cp16(bb + OFF_B + row * 80 + c * 16,
                 W + (size_t)(col0 + row) * K + s * 32 + c * 8);
        }
        asm volatile("cp.async.commit_group;");
    };

    // ---- compute one staged BK=32 chunk ----
    auto compute = [&](int s) {
        const uint32_t base = AB + (uint32_t)(s & 3) * STAGE_B;
#pragma unroll
        for (int kk = 0; kk < 32; kk += 16) {
            uint32_t af[2][4], bf[2][4];
#pragma unroll
            for (int i = 0; i < 2; i++) {
                uint32_t row = wm * 32 + i * 16 + (lane & 15);
                uint32_t cb = (kk + ((lane >> 4) << 3)) * 2;
                ldm_x4(af[i], base + OFF_A + row * 80 + cb);
            }
#pragma unroll
            for (int jp = 0; jp < 2; jp++) {
                uint32_t row = wn * 32 + jp * 16 + (lane & 7) + ((lane >> 4) << 3);
                uint32_t cb = (kk + (((lane >> 3) & 1) << 3)) * 2;
                ldm_x4(bf[jp], base + OFF_B + row * 80 + cb);
            }
#pragma unroll
            for (int i = 0; i < 2; i++)
#pragma unroll
                for (int j = 0; j < 4; j++)
                    mma_fp16(acc[i][j], af[i], &bf[j >> 1][(j & 1) * 2]);
        }
    };

    // ---- depth-2 pipeline, 4 buffers, ONE barrier per chunk ----
    stage_load(0);
    stage_load(1);
#pragma unroll 1
    for (int s = 0; s < S; s++) {
        if (s + 2 < S) {
            stage_load(s + 2);
            asm volatile("cp.async.wait_group 2;" ::: "memory");
        } else if (s + 1 < S) {
            asm volatile("cp.async.wait_group 1;" ::: "memory");
        } else {
            asm volatile("cp.async.wait_group 0;" ::: "memory");
        }
        __syncthreads();
        compute(s);
    }

    // ---- fused LSTM epilogue ----
    // acc[i][j]: c0,c1=(m=g, n=2t,2t+1), c2,c3=(m=g+8, same n) at
    // (m = wm*32+i*16, n' = wn*32+j*8). lane^1 shuffle reassembles gate quads.
    const bool ev = (tq & 1) == 0;
    const int mrow = row0 + wm * 32 + g + (ev ? 0 : 8);
    __half* hout = hB + (MODE == 0 ? 0 : 256);
#pragma unroll
    for (int i = 0; i < 2; i++) {
        const int m = mrow + i * 16;
#pragma unroll
        for (int j = 0; j < 4; j++) {
            float* a = acc[i][j];
            float s0 = ev ? a[2] : a[0];
            float s1 = ev ? a[3] : a[1];
            float r0 = __shfl_xor_sync(0xFFFFFFFFu, s0, 1);
            float r1 = __shfl_xor_sync(0xFFFFFFFFu, s1, 1);
            float zi = ev ? a[0] : r0;
            float zf = ev ? a[1] : r1;
            float zg = ev ? r0 : a[2];
            float zo = ev ? r1 : a[3];
            int ul = wn * 8 + j * 2 + (tq >> 1);
            float4 bz = *(const float4*)(bias + col0 + 4 * ul);
            int ug = (col0 >> 2) + ul;
            zi += bz.x; zf += bz.y; zg += bz.z; zo += bz.w;
            float cold = cbuf[(size_t)m * HH + ug];
            float c2 = fsig(zf) * cold + fsig(zi) * ftanh(zg);
            float hv = fsig(zo) * ftanh(c2);
            cbuf[(size_t)m * HH + ug] = c2;
            hout[(size_t)m * 512 + ug] = __float2half(hv);
        }
    }
}

// ---------------- projection + softplus + CRPS ----------------
__device__ __forceinline__ float softplusf(float x) {
    return fmaxf(x, 0.f) + log1pf(expf(-fabsf(x)));
}

__global__ void proj_crps(const float* __restrict__ labels, int t, int rd,
                          float* __restrict__ out)
{
    int b = blockIdx.x;
    int lane = threadIdx.x;
    const __half* hrow = (rd ? g_h0 : g_h1) + (size_t)b * 512;

    float hreg[16];
#pragma unroll
    for (int j = 0; j < 16; j++) hreg[j] = __half2float(hrow[lane + 32 * j]);

    __shared__ float sp[21];
    for (int m = 0; m < 21; m++) {
        const float* wv = g_Wp + m * 512;
        float a = 0.f;
#pragma unroll
        for (int j = 0; j < 16; j++) a += hreg[j] * wv[lane + 32 * j];
#pragma unroll
        for (int o = 16; o; o >>= 1) a += __shfl_xor_sync(0xFFFFFFFFu, a, o);
        if (lane == 0) sp[m] = softplusf(a + g_pb[m]);
    }
    __syncwarp();

    if (lane == 0) {
        const float invk = 1.0f / (float)KSEG;
        float beta0 = sp[0];
        float g[KSEG];
#pragma unroll
        for (int j = 0; j < KSEG; j++) g[j] = sp[1 + j];

        float braw[KSEG];
        braw[0] = (g[0] - beta0) * (0.5f * KSEG);
#pragma unroll
        for (int i = 1; i < KSEG; i++) braw[i] = (g[i] - g[i - 1]) * (0.5f * KSEG);
        float bb[KSEG];
        bb[0] = braw[0];
#pragma unroll
        for (int i = 1; i < KSEG; i++) bb[i] = braw[i] - braw[i - 1];
        float ssum = 0.f;
#pragma unroll
        for (int i = 0; i < KSEG - 1; i++) ssum += bb[i];
        bb[KSEG - 1] = g[KSEG - 1] - ssum;

        float F[KSEG];
        for (int i = 0; i < KSEG; i++) {
            float acc = (float)(i + 1) * invk * beta0;
            for (int j = 0; j <= i; j++) {
                float d = (float)(i + 1 - j) * invk;
                acc += d * d * bb[j];
            }
            F[i] = acc;
        }

        float y = labels[b * TT + t];
        float A = 0.f, Bc = beta0, C = -y;
        float mind = 1e30f; int amin = 0;
        unsigned almask = 0;
        for (int i = 0; i < KSEG; i++) {
            float knot = (i == 0) ? 0.f : F[i - 1];
            float diff = y - knot;
            float ad = fabsf(diff);
            if (ad < mind) { mind = ad; amin = i; }
            if (diff > 0.f) {
                almask |= (1u << i);
                float ksi = (float)i * invk;
                A += bb[i];
                Bc -= 2.f * bb[i] * ksi;
                C += bb[i] * ksi * ksi;
            }
        }
        float disc = Bc * Bc - 4.f * A * C;
        float alpha;
        if (A != 0.f && disc >= 0.f)       alpha = (-Bc + sqrtf(disc)) / (2.f * A);
        else if (A == 0.f)                 alpha = -C / ((Bc == 0.f) ? 1.f : Bc);
        else                               alpha = (float)amin * invk;

        float crps = -y * (1.f - 2.f * alpha) + beta0 * (1.f / 3.f - alpha * alpha);
        for (int i = 0; i < KSEG; i++) {
            float ksi = (float)i * invk;
            float om = 1.f - ksi;
            crps += bb[i] * (1.f / 6.f) * om * om * om * om;
            if ((almask >> i) & 1u) {
                float d = alpha - ksi;
                crps -= (2.f / 3.f) * bb[i] * d * d * d;
            }
        }
        atomicAdd(out, crps * (1.0f / (float)BSZ));
    }
}

// ---------------- host launch ----------------
extern "C" void kernel_launch(void* const* d_in, const int* in_sizes, int n_in,
                              void* d_out, int out_size)
{
    const float* train  = (const float*)d_in[0];
    const float* labels = (const float*)d_in[1];
    const float* Wih0 = (const float*)d_in[2];
    const float* Whh0 = (const float*)d_in[3];
    const float* Wih1 = (const float*)d_in[4];
    const float* Whh1 = (const float*)d_in[5];
    const float* bih0 = (const float*)d_in[6];
    const float* bhh0 = (const float*)d_in[7];
    const float* bih1 = (const float*)d_in[8];
    const float* bhh1 = (const float*)d_in[9];
    const float* Wpb  = (const float*)d_in[10];
    const float* bpb  = (const float*)d_in[11];
    const float* Wpg  = (const float*)d_in[12];
    const float* bpg  = (const float*)d_in[13];
    float* out = (float*)d_out;

    cudaFuncSetAttribute(gemm_step<0>, cudaFuncAttributeMaxDynamicSharedMemorySize, SMEM_REQ);
    cudaFuncSetAttribute(gemm_step<1>, cudaFuncAttributeMaxDynamicSharedMemorySize, SMEM_REQ);

    zero_state<<<(BSZ * 512 + 255) / 256, 256>>>(out);
    presplit_x<<<(BSZ * TT * DIN + 255) / 256, 256>>>(train);
    build_weights<<<(1024 * 512 + 255) / 256, 256>>>(
        Wih0, Whh0, Wih1, Whh1, bih0, bhh0, bih1, bhh1, Wpb, bpb, Wpg, bpg);

    dim3 grid(8, 32);   // (N tiles of 128, M tiles of 64) = 256 CTAs
    for (int t = 0; t < TT; t++) {
        int rd = t & 1;
        gemm_step<0><<<grid, NTHREADS, SMEM_REQ>>>(rd, t);
        gemm_step<1><<<grid, NTHREADS, SMEM_REQ>>>(rd, t);
        proj_crps<<<BSZ, 32>>>(labels, t, rd, out);
    }
}